// round 3
// baseline (speedup 1.0000x reference)
#include <cuda_runtime.h>

// Sepconv: out[b,c,y,x] = sum_{i,j} in[b,c,5y+i,5x+j] * V[b,i,y,x] * H[b,j,y,x]
// B=8, C=3, F=5, HO=WO=256. Pure HBM-bound (~185 MB compulsory traffic).
//
// R3: no smem, no barriers. 4 outputs per thread in x -> each (channel,row)
// footprint is 20 contiguous floats at an 80B-aligned offset = 5 aligned
// LDG.128, every sector touched exactly once. 85 independent vector loads
// per thread keeps the DRAM queue dense without any sync bubbles.

#define B_ 8
#define C_ 3
#define F_ 5
#define HO_ 256
#define WO_ 256
#define HI_ (HO_ * F_)
#define WI_ (WO_ * F_)
#define QX_ (WO_ / 4)                 // 64 x-quads per row

__global__ __launch_bounds__(256) void sepconv_v4_kernel(
    const float* __restrict__ in,
    const float* __restrict__ V,
    const float* __restrict__ H,
    float* __restrict__ out)
{
    const int t = blockIdx.x * blockDim.x + threadIdx.x;
    if (t >= B_ * HO_ * QX_) return;

    const int xq = t % QX_;
    const int y  = (t / QX_) % HO_;
    const int b  = t / (QX_ * HO_);

    // Weights for the 4 outputs: V/H[b,i,y,4xq..4xq+3], float4-aligned.
    // Unpack to scalar arrays: vm[i][u], hm[j][u].
    float vm[F_][4], hm[F_][4];
    {
        const int sbase = (b * F_) * (HO_ * WO_) + y * WO_ + xq * 4;
#pragma unroll
        for (int i = 0; i < F_; i++) {
            float4 vv = *reinterpret_cast<const float4*>(V + sbase + i * (HO_ * WO_));
            float4 hh = *reinterpret_cast<const float4*>(H + sbase + i * (HO_ * WO_));
            vm[i][0] = vv.x; vm[i][1] = vv.y; vm[i][2] = vv.z; vm[i][3] = vv.w;
            hm[i][0] = hh.x; hm[i][1] = hh.y; hm[i][2] = hh.z; hm[i][3] = hh.w;
        }
    }

#pragma unroll
    for (int c = 0; c < C_; c++) {
        const float* base = in
            + ((long long)((b * C_ + c) * HI_ + y * F_)) * WI_
            + xq * 20;                         // 80B offset, float4-aligned
        float acc[4] = {0.f, 0.f, 0.f, 0.f};

#pragma unroll
        for (int i = 0; i < F_; i++) {
            // 20 contiguous floats = 5 aligned LDG.128
            const float4* rp = reinterpret_cast<const float4*>(base + i * WI_);
            float4 r0 = rp[0], r1 = rp[1], r2 = rp[2], r3 = rp[3], r4 = rp[4];
            float f[20];
            f[0]=r0.x;  f[1]=r0.y;  f[2]=r0.z;  f[3]=r0.w;
            f[4]=r1.x;  f[5]=r1.y;  f[6]=r1.z;  f[7]=r1.w;
            f[8]=r2.x;  f[9]=r2.y;  f[10]=r2.z; f[11]=r2.w;
            f[12]=r3.x; f[13]=r3.y; f[14]=r3.z; f[15]=r3.w;
            f[16]=r4.x; f[17]=r4.y; f[18]=r4.z; f[19]=r4.w;

#pragma unroll
            for (int u = 0; u < 4; u++) {
                float rs = 0.f;
#pragma unroll
                for (int j = 0; j < F_; j++)
                    rs = fmaf(f[5 * u + j], hm[j][u], rs);
                acc[u] = fmaf(rs, vm[i][u], acc[u]);
            }
        }

        float4 o;
        o.x = acc[0]; o.y = acc[1]; o.z = acc[2]; o.w = acc[3];
        *reinterpret_cast<float4*>(
            out + ((b * C_ + c) * HO_ + y) * WO_ + xq * 4) = o;
    }
}

extern "C" void kernel_launch(void* const* d_in, const int* in_sizes, int n_in,
                              void* d_out, int out_size)
{
    const float* in  = (const float*)d_in[0];  // [8,3,1280,1280]
    const float* V   = (const float*)d_in[1];  // [8,5,256,256]
    const float* H   = (const float*)d_in[2];  // [8,5,256,256]
    float* out = (float*)d_out;                // [8,3,256,256]

    const int total = B_ * HO_ * QX_;          // 131072 threads
    const int threads = 256;
    const int blocks = (total + threads - 1) / threads;   // 512
    sepconv_v4_kernel<<<blocks, threads>>>(in, V, H, out);
}

// round 4
// speedup vs baseline: 1.3051x; 1.3051x over previous
#include <cuda_runtime.h>
#include <cstdint>

// Sepconv: out[b,c,y,x] = sum_{i,j} in[b,c,5y+i,5x+j] * V[b,i,y,x] * H[b,j,y,x]
// B=8, C=3, F=5, HO=WO=256. HBM-bound (~185 MB compulsory traffic).
//
// R4: R2's block-per-(b,y) smem staging, but the strip load goes through
// cp.async (LDGSTS) with two buffers: channels double-buffered so the DRAM
// request stream never drains at the per-channel __syncthreads boundaries.

#define B_ 8
#define C_ 3
#define F_ 5
#define HO_ 256
#define WO_ 256
#define HI_ (HO_ * F_)
#define WI_ (WO_ * F_)

#define TILE_FLOATS (F_ * WI_)        // 6400 floats = 25.6 KB
#define TILE_VEC4   (TILE_FLOATS / 4) // 1600 float4
#define FULL_PASSES (TILE_VEC4 / 256) // 6
#define REM_VEC4    (TILE_VEC4 - FULL_PASSES * 256) // 64

__device__ __forceinline__ void cp16(uint32_t dst_smem, const float4* src) {
    asm volatile("cp.async.cg.shared.global [%0], [%1], 16;\n"
                 :: "r"(dst_smem), "l"(src));
}
__device__ __forceinline__ void cp_commit() {
    asm volatile("cp.async.commit_group;\n");
}
template <int N>
__device__ __forceinline__ void cp_wait() {
    asm volatile("cp.async.wait_group %0;\n" :: "n"(N));
}

__global__ __launch_bounds__(256) void sepconv_pipe_kernel(
    const float* __restrict__ in,
    const float* __restrict__ V,
    const float* __restrict__ H,
    float* __restrict__ out)
{
    extern __shared__ float smem[];   // 2 * TILE_FLOATS

    const int tid = threadIdx.x;
    const int y = blockIdx.x % HO_;
    const int b = blockIdx.x / HO_;

    float* buf[2] = { smem, smem + TILE_FLOATS };
    uint32_t sbuf[2];
    sbuf[0] = (uint32_t)__cvta_generic_to_shared(buf[0]);
    sbuf[1] = (uint32_t)__cvta_generic_to_shared(buf[1]);

    // Issue one channel's 5-row strip (6400 contiguous floats) as cp.async.
    auto issue = [&](int c, uint32_t dst) {
        const float4* src = reinterpret_cast<const float4*>(
            in + ((long long)((b * C_ + c) * HI_ + y * F_)) * WI_);
#pragma unroll
        for (int k = 0; k < FULL_PASSES; k++)
            cp16(dst + (uint32_t)(tid + k * 256) * 16u, src + tid + k * 256);
        if (tid < REM_VEC4)
            cp16(dst + (uint32_t)(tid + FULL_PASSES * 256) * 16u,
                 src + tid + FULL_PASSES * 256);
        cp_commit();
    };

    issue(0, sbuf[0]);   // group 0
    issue(1, sbuf[1]);   // group 1

    // Per-thread weights for (b, y, x=tid); overlaps with cp.async in flight.
    float v[F_], h[F_];
    {
        const int sbase = (b * F_) * (HO_ * WO_) + y * WO_ + tid;
#pragma unroll
        for (int i = 0; i < F_; i++) {
            v[i] = V[sbase + i * (HO_ * WO_)];
            h[i] = H[sbase + i * (HO_ * WO_)];
        }
    }

    auto compute = [&](int c, const float* s) {
        float acc = 0.0f;
#pragma unroll
        for (int i = 0; i < F_; i++) {
            const float* row = s + i * WI_ + tid * F_;
            float rs = 0.0f;
#pragma unroll
            for (int j = 0; j < F_; j++)
                rs = fmaf(row[j], h[j], rs);
            acc = fmaf(rs, v[i], acc);
        }
        out[((b * C_ + c) * HO_ + y) * WO_ + tid] = acc;
    };

    // c = 0
    cp_wait<1>();            // group 0 (c0) complete
    __syncthreads();
    compute(0, buf[0]);
    __syncthreads();         // everyone done reading buf0
    issue(2, sbuf[0]);       // group 2 -> buf0

    // c = 1
    cp_wait<1>();            // group 1 (c1) complete
    __syncthreads();
    compute(1, buf[1]);

    // c = 2
    cp_wait<0>();            // group 2 (c2) complete
    __syncthreads();
    compute(2, buf[0]);
}

extern "C" void kernel_launch(void* const* d_in, const int* in_sizes, int n_in,
                              void* d_out, int out_size)
{
    const float* in  = (const float*)d_in[0];  // [8,3,1280,1280]
    const float* V   = (const float*)d_in[1];  // [8,5,256,256]
    const float* H   = (const float*)d_in[2];  // [8,5,256,256]
    float* out = (float*)d_out;                // [8,3,256,256]

    const int smem_bytes = 2 * TILE_FLOATS * (int)sizeof(float);  // 51200
    cudaFuncSetAttribute(sepconv_pipe_kernel,
                         cudaFuncAttributeMaxDynamicSharedMemorySize,
                         smem_bytes);

    const int blocks = B_ * HO_;               // 2048, one per (b,y)
    sepconv_pipe_kernel<<<blocks, 256, smem_bytes>>>(in, V, H, out);
}

// round 5
// speedup vs baseline: 1.3323x; 1.0209x over previous
#include <cuda_runtime.h>
#include <cstdint>

// Sepconv: out[b,c,y,x] = sum_{i,j} in[b,c,5y+i,5x+j] * V[b,i,y,x] * H[b,j,y,x]
// B=8, C=3, F=5, HO=WO=256. HBM-bound (~180 MB compulsory traffic).
//
// R5: finer granularity + fully front-loaded pipeline.
// Block = 128 threads = half an output row (128 x-positions). Per channel the
// input strip is 5 rows x 640 floats = 12.8 KB. THREE smem buffers; all three
// channel cp.async groups are issued at block start (no mid-block re-issue),
// computes drain them in order. 4096 blocks -> ~27 blocks/SM, fine-grained tail.

#define B_ 8
#define C_ 3
#define F_ 5
#define HO_ 256
#define WO_ 256
#define HI_ (HO_ * F_)
#define WI_ (WO_ * F_)

#define HALF_W   (WO_ / 2)               // 128 outputs per block
#define STRIP_W  (HALF_W * F_)           // 640 floats per input row chunk
#define TILE_FLOATS (F_ * STRIP_W)       // 3200 floats = 12.8 KB
#define TILE_VEC4   (TILE_FLOATS / 4)    // 800 float4
#define NT 128
#define FULL_PASSES (TILE_VEC4 / NT)     // 6
#define REM_VEC4    (TILE_VEC4 - FULL_PASSES * NT)  // 32

__device__ __forceinline__ void cp16(uint32_t dst_smem, const float4* src) {
    asm volatile("cp.async.cg.shared.global [%0], [%1], 16;\n"
                 :: "r"(dst_smem), "l"(src));
}
__device__ __forceinline__ void cp_commit() {
    asm volatile("cp.async.commit_group;\n");
}
template <int N>
__device__ __forceinline__ void cp_wait() {
    asm volatile("cp.async.wait_group %0;\n" :: "n"(N));
}

__global__ __launch_bounds__(NT) void sepconv_pipe3_kernel(
    const float* __restrict__ in,
    const float* __restrict__ V,
    const float* __restrict__ H,
    float* __restrict__ out)
{
    extern __shared__ float smem[];      // 3 * TILE_FLOATS

    const int tid  = threadIdx.x;        // 0..127
    const int half = blockIdx.x & 1;     // which half of the row
    const int y    = (blockIdx.x >> 1) % HO_;
    const int b    = blockIdx.x >> 1 >> 8;

    const int x0 = half * HALF_W;        // starting output x for this block

    uint32_t sbase_u = (uint32_t)__cvta_generic_to_shared(smem);

    // Issue all three channel strips up-front. Each strip: 5 rows of 640
    // contiguous floats (row stride WI_=1280). 2560B rows, float4-aligned.
    const long long in_base = ((long long)(b * C_) * HI_ + (long long)y * F_) * WI_
                              + (long long)x0 * F_;
#pragma unroll
    for (int c = 0; c < C_; c++) {
        const float* strip = in + in_base + (long long)c * HI_ * WI_;
        uint32_t dst = sbase_u + (uint32_t)(c * TILE_FLOATS) * 4u;
        // TILE_VEC4 = 800 = 6*128 + 32; map linear index -> (row, col4)
#pragma unroll
        for (int k = 0; k < FULL_PASSES; k++) {
            int idx = tid + k * NT;                  // 0..767
            int row = idx / (STRIP_W / 4);           // /160
            int col = idx % (STRIP_W / 4);
            cp16(dst + (uint32_t)idx * 16u,
                 reinterpret_cast<const float4*>(strip + row * WI_) + col);
        }
        if (tid < REM_VEC4) {
            int idx = tid + FULL_PASSES * NT;        // 768..799
            int row = idx / (STRIP_W / 4);
            int col = idx % (STRIP_W / 4);
            cp16(dst + (uint32_t)idx * 16u,
                 reinterpret_cast<const float4*>(strip + row * WI_) + col);
        }
        cp_commit();
    }

    // Weights for (b, y, x0+tid): coalesced, overlap with cp.async in flight.
    float v[F_], h[F_];
    {
        const int sb = (b * F_) * (HO_ * WO_) + y * WO_ + x0 + tid;
#pragma unroll
        for (int i = 0; i < F_; i++) {
            v[i] = V[sb + i * (HO_ * WO_)];
            h[i] = H[sb + i * (HO_ * WO_)];
        }
    }

    auto compute = [&](int c) {
        const float* s = smem + c * TILE_FLOATS;
        float acc = 0.0f;
#pragma unroll
        for (int i = 0; i < F_; i++) {
            const float* row = s + i * STRIP_W + tid * F_;
            float rs = 0.0f;
#pragma unroll
            for (int j = 0; j < F_; j++)
                rs = fmaf(row[j], h[j], rs);
            acc = fmaf(rs, v[i], acc);
        }
        out[((b * C_ + c) * HO_ + y) * WO_ + x0 + tid] = acc;
    };

    cp_wait<2>();  __syncthreads();  compute(0);
    cp_wait<1>();  __syncthreads();  compute(1);
    cp_wait<0>();  __syncthreads();  compute(2);
}

extern "C" void kernel_launch(void* const* d_in, const int* in_sizes, int n_in,
                              void* d_out, int out_size)
{
    const float* in  = (const float*)d_in[0];  // [8,3,1280,1280]
    const float* V   = (const float*)d_in[1];  // [8,5,256,256]
    const float* H   = (const float*)d_in[2];  // [8,5,256,256]
    float* out = (float*)d_out;                // [8,3,256,256]

    const int smem_bytes = 3 * TILE_FLOATS * (int)sizeof(float);  // 38400

    const int blocks = B_ * HO_ * 2;           // 4096: (b, y, half)
    sepconv_pipe3_kernel<<<blocks, NT, smem_bytes>>>(in, V, H, out);
}